// round 5
// baseline (speedup 1.0000x reference)
#include <cuda_runtime.h>
#include <cstdint>
#include <math.h>

// Problem constants (fixed by the dataset)
#define NTOK 32768   // B*T = 8*4096
#define DDIM 1024
#define NEXP 64

// Tiling
#define BM 64        // tokens per block
#define BK 16        // K chunk
#define BN 128       // 64 route + 64 noise outputs
#define THREADS 256
#define NKT (DDIM / BK)   // 64 K-tiles
#define EP 65        // padded epilogue row (bank-conflict-free column scans)

struct SmemT {
    union {
        struct {                    // double-buffered GEMM stage (24 KB)
            float xs[2][BM][BK];    // 8 KB  token x chunk
            float ws[2][BK][BN];    // 16 KB weight chunk (route | noise)
        } g;
        struct {                    // epilogue stage (33.3 KB) — the union max
            float sp[BM][EP];       // softplus(noise_logit + b_noise)
            float noisy[BM][EP];    // final noisy logits
        } e;
    };
};

__device__ __forceinline__ unsigned long long pack2(float a, float b) {
    unsigned long long r;
    asm("mov.b64 %0, {%1, %2};" : "=l"(r) : "f"(a), "f"(b));
    return r;
}
__device__ __forceinline__ void unpack2(unsigned long long v, float& lo, float& hi) {
    asm("mov.b64 {%0, %1}, %2;" : "=f"(lo), "=f"(hi) : "l"(v));
}
// Packed dual fp32 FMA (Blackwell f32x2 pipe) — IEEE fp32 per lane, so
// numerics are identical to scalar FFMA (top-k ordering stays exact).
__device__ __forceinline__ void fma2(unsigned long long& d,
                                     unsigned long long a,
                                     unsigned long long b) {
    asm("fma.rn.f32x2 %0, %1, %2, %0;" : "+l"(d) : "l"(a), "l"(b));
}

__device__ __forceinline__ float softplus_f(float z) {
    // log1p(exp(z)) computed stably: max(z,0) + log1p(exp(-|z|))
    return fmaxf(z, 0.0f) + log1pf(expf(-fabsf(z)));
}

__global__ __launch_bounds__(THREADS, 2)
void router_kernel(const float* __restrict__ x,
                   const float* __restrict__ Wr,
                   const float* __restrict__ br,
                   const float* __restrict__ Wn,
                   const float* __restrict__ bn,
                   const float* __restrict__ u,
                   float* __restrict__ out) {
    __shared__ SmemT s;

    const int tid  = threadIdx.x;
    const int tx   = tid & 15;    // output-group id (0..15): 8 outputs each
    const int ty   = tid >> 4;    // token-group id  (0..15): 4 tokens each
    const int tok0 = blockIdx.x * BM;

    // ---------------- GEMM: acc[4 tokens][4 output-pairs] ----------------
    unsigned long long acc[4][4] = {};

    // staging-load index split (global -> regs)
    const int xrow = tid >> 2;          // 0..63
    const int xcol = (tid & 3) * 4;     // 0,4,8,12
    const int wk0  = tid >> 5;          // 0..7
    const int wk1  = 8 + wk0;           // 8..15
    const int wn   = (tid & 31) * 4;    // 0..124

    auto ld_x = [&](int k0) -> float4 {
        return *(const float4*)&x[(size_t)(tok0 + xrow) * DDIM + k0 + xcol];
    };
    auto ld_w = [&](int k0, int k) -> float4 {
        const float* src = (wn < 64)
            ? &Wr[(size_t)(k0 + k) * NEXP + wn]
            : &Wn[(size_t)(k0 + k) * NEXP + (wn - 64)];
        return *(const float4*)src;
    };

    // prologue: stage tile 0 into buffer 0
    {
        float4 sx  = ld_x(0);
        float4 sw0 = ld_w(0, wk0);
        float4 sw1 = ld_w(0, wk1);
        *(float4*)&s.g.xs[0][xrow][xcol] = sx;
        *(float4*)&s.g.ws[0][wk0][wn]    = sw0;
        *(float4*)&s.g.ws[0][wk1][wn]    = sw1;
    }
    __syncthreads();

    for (int kt = 0; kt < NKT; ++kt) {
        const int cur = kt & 1;

        // prefetch next tile (global -> regs) before chewing on current one
        float4 sx, sw0, sw1;
        if (kt < NKT - 1) {
            int k0 = (kt + 1) * BK;
            sx  = ld_x(k0);
            sw0 = ld_w(k0, wk0);
            sw1 = ld_w(k0, wk1);
        }

        #pragma unroll
        for (int kk = 0; kk < BK; ++kk) {
            // 8 outputs for this thread = 4 packed pairs, contiguous in smem
            const ulonglong2* bp = (const ulonglong2*)&s.g.ws[cur][kk][tx * 8];
            ulonglong2 b01 = bp[0];
            ulonglong2 b23 = bp[1];
            #pragma unroll
            for (int i = 0; i < 4; ++i) {
                float av = s.g.xs[cur][ty * 4 + i][kk];
                unsigned long long a2 = pack2(av, av);
                fma2(acc[i][0], a2, b01.x);
                fma2(acc[i][1], a2, b01.y);
                fma2(acc[i][2], a2, b23.x);
                fma2(acc[i][3], a2, b23.y);
            }
        }

        // store prefetched tile into the other buffer (no conflict with the
        // reads above; the end-of-iteration sync makes it visible)
        if (kt < NKT - 1) {
            const int nxt = cur ^ 1;
            *(float4*)&s.g.xs[nxt][xrow][xcol] = sx;
            *(float4*)&s.g.ws[nxt][wk0][wn]    = sw0;
            *(float4*)&s.g.ws[nxt][wk1][wn]    = sw1;
        }
        __syncthreads();   // one barrier per K-tile
    }

    // ---------------- Epilogue ----------------
    // Threads tx>=8 hold noise logits (outputs 64..127): write softplus to smem.
    if (tx >= 8) {
        int e0 = (tx - 8) * 8;
        #pragma unroll
        for (int i = 0; i < 4; ++i) {
            int t = ty * 4 + i;
            #pragma unroll
            for (int j = 0; j < 4; ++j) {
                float lo, hi;
                unpack2(acc[i][j], lo, hi);
                int e = e0 + 2 * j;
                s.e.sp[t][e]     = softplus_f(lo + bn[e]);
                s.e.sp[t][e + 1] = softplus_f(hi + bn[e + 1]);
            }
        }
    }
    __syncthreads();

    // Threads tx<8 hold route logits: combine with noise term into noisy smem.
    if (tx < 8) {
        int e0 = tx * 8;
        #pragma unroll
        for (int i = 0; i < 4; ++i) {
            int t = ty * 4 + i;
            size_t tg = (size_t)(tok0 + t);
            #pragma unroll
            for (int j = 0; j < 4; ++j) {
                float lo, hi;
                unpack2(acc[i][j], lo, hi);
                int e = e0 + 2 * j;
                float2 uu = *(const float2*)&u[tg * NEXP + e];
                s.e.noisy[t][e]     = lo + br[e]     + uu.x * s.e.sp[t][e];
                s.e.noisy[t][e + 1] = hi + br[e + 1] + uu.y * s.e.sp[t][e + 1];
            }
        }
    }
    __syncthreads();

    // One thread per token: top-2 scan + sparse softmax + indices.
    if (tid < BM) {
        int t = tid;
        float m1 = -INFINITY, m2 = -INFINITY;
        int i1 = 0, i2 = 0;
        #pragma unroll
        for (int e = 0; e < NEXP; ++e) {
            float v = s.e.noisy[t][e];
            if (v > m1) { m2 = m1; i2 = i1; m1 = v; i1 = e; }
            else if (v > m2) { m2 = v; i2 = e; }
        }
        float ex  = expf(m2 - m1);
        float inv = 1.0f / (1.0f + ex);
        float p1 = inv, p2 = ex * inv;

        float* rowp = out + (size_t)(tok0 + t) * NEXP;
        #pragma unroll
        for (int q = 0; q < NEXP / 4; ++q) {
            int eb = q * 4;
            float4 v;
            v.x = (eb + 0 == i1) ? p1 : ((eb + 0 == i2) ? p2 : 0.0f);
            v.y = (eb + 1 == i1) ? p1 : ((eb + 1 == i2) ? p2 : 0.0f);
            v.z = (eb + 2 == i1) ? p1 : ((eb + 2 == i2) ? p2 : 0.0f);
            v.w = (eb + 3 == i1) ? p1 : ((eb + 3 == i2) ? p2 : 0.0f);
            ((float4*)rowp)[q] = v;
        }
        float* ip = out + (size_t)NTOK * NEXP + (size_t)(tok0 + t) * 2;
        ip[0] = (float)i1;
        ip[1] = (float)i2;
    }
}

extern "C" void kernel_launch(void* const* d_in, const int* in_sizes, int n_in,
                              void* d_out, int out_size) {
    const float* x  = (const float*)d_in[0];  // mh_output [B,T,D]
    const float* Wr = (const float*)d_in[1];  // W_route   [D,E]
    const float* br = (const float*)d_in[2];  // b_route   [E]
    const float* Wn = (const float*)d_in[3];  // W_noise   [D,E]
    const float* bn = (const float*)d_in[4];  // b_noise   [E]
    const float* u  = (const float*)d_in[5];  // noise_u   [B,T,E]
    // d_in[6] = top_k (compile-time K=2)

    router_kernel<<<NTOK / BM, THREADS>>>(x, Wr, br, Wn, bn, u, (float*)d_out);
}

// round 15
// speedup vs baseline: 2.5857x; 2.5857x over previous
#include <cuda_runtime.h>
#include <cuda_bf16.h>
#include <cstdint>
#include <math.h>

// ---------------- problem constants ----------------
#define NTOK 32768
#define DDIM 1024
#define NEXP 64
#define NOUT 128              // 64 route | 64 noise
#define TILE_M 128            // tokens per CTA
#define KC 32                 // K per staged chunk
#define NC (DDIM / KC)        // 32 chunks
#define THREADS 256
#define NCTA (NTOK / TILE_M)  // 256
#define EPS_MARGIN 2e-3f      // >=200x TC+split logit error; flags ~0.3% of tokens

// smem staging: rows of 64B (32 bf16), XOR-swizzled
#define PLANE 8192                    // 128 rows * 64 B
#define BS_BASE (4 * PLANE)           // B planes after A planes (2 bufs x 2 planes)
#define CV_STRIDE 133                 // epilogue canvas row stride (floats)
#define US_BASE 68096                 // 128*133*4
#define US_STRIDE 65
#define BAD_BASE (US_BASE + 128 * US_STRIDE * 4)   // 101376
#define CNT_BASE (BAD_BASE + 128 * 4)              // 101888
#define SMEM_TOTAL (CNT_BASE + 16)                 // 101904

// pre-split bf16 weight planes wb[plane][n][k] + exact fp32 transpose wt[n][k]
__device__ unsigned short g_wb[2 * NOUT * DDIM];   // 512 KB
__device__ float          g_wt[NOUT * DDIM];       // 512 KB

// ---------------- helpers ----------------
__device__ __forceinline__ unsigned smem_u32(const void* p) {
    unsigned a;
    asm("{ .reg .u64 t; cvta.to.shared.u64 t, %1; cvt.u32.u64 %0, t; }" : "=r"(a) : "l"(p));
    return a;
}
// 16B-granular XOR swizzle within a 64B row
__device__ __forceinline__ unsigned sw(int row, unsigned byteoff) {
    return byteoff ^ ((((unsigned)row >> 1) & 3u) << 4);
}
__device__ __forceinline__ int a_plane(int buf, int p) { return (buf * 2 + p) * PLANE; }
__device__ __forceinline__ int b_plane(int buf, int p) { return BS_BASE + (buf * 2 + p) * PLANE; }

__device__ __forceinline__ void cp16(unsigned dst, const void* src) {
    asm volatile("cp.async.cg.shared.global [%0], [%1], 16;" :: "r"(dst), "l"(src) : "memory");
}
__device__ __forceinline__ void ldm4(unsigned* r, unsigned addr) {
    asm volatile("ldmatrix.sync.aligned.m8n8.x4.shared.b16 {%0,%1,%2,%3}, [%4];"
                 : "=r"(r[0]), "=r"(r[1]), "=r"(r[2]), "=r"(r[3]) : "r"(addr));
}
__device__ __forceinline__ void mma_bf16(float* c, const unsigned* a, unsigned b0, unsigned b1) {
    asm volatile(
        "mma.sync.aligned.m16n8k16.row.col.f32.bf16.bf16.f32 "
        "{%0,%1,%2,%3}, {%4,%5,%6,%7}, {%8,%9}, {%0,%1,%2,%3};"
        : "+f"(c[0]), "+f"(c[1]), "+f"(c[2]), "+f"(c[3])
        : "r"(a[0]), "r"(a[1]), "r"(a[2]), "r"(a[3]), "r"(b0), "r"(b1));
}

// exact 2-way bf16 split (18-bit combined mantissa; decisions protected by re-check)
__device__ __forceinline__ void split2(float v, unsigned short& h1, unsigned short& h2) {
    __nv_bfloat16 b1 = __float2bfloat16_rn(v);
    float r = v - __bfloat162float(b1);
    __nv_bfloat16 b2 = __float2bfloat16_rn(r);
    h1 = __bfloat16_as_ushort(b1);
    h2 = __bfloat16_as_ushort(b2);
}

__device__ __forceinline__ float softplus_f(float z) {
    return fmaxf(z, 0.0f) + log1pf(expf(-fabsf(z)));
}

// ---------------- prep kernel ----------------
__global__ void prep_w(const float* __restrict__ Wr, const float* __restrict__ Wn) {
    int id = blockIdx.x * blockDim.x + threadIdx.x;   // 0..131071
    int n = id >> 10;          // 0..127
    int k = id & 1023;
    float w = (n < 64) ? Wr[k * 64 + n] : Wn[k * 64 + (n - 64)];
    unsigned short h1, h2;
    split2(w, h1, h2);
    int idx = n * DDIM + k;
    g_wb[idx]          = h1;
    g_wb[131072 + idx] = h2;
    g_wt[idx]          = w;
}

// ---------------- main fused kernel ----------------
__global__ __launch_bounds__(THREADS, 2)
void router_mma_kernel(const float* __restrict__ x,
                       const float* __restrict__ br,
                       const float* __restrict__ bn,
                       const float* __restrict__ u,
                       float* __restrict__ out) {
    extern __shared__ unsigned char smbuf[];
    const unsigned sb = smem_u32(smbuf);
    const int tid  = threadIdx.x;
    const int wid  = tid >> 5;
    const int lane = tid & 31;
    const int tok0 = blockIdx.x * TILE_M;
    const int mrow = (wid & 3) * 32;
    const int ncol = (wid >> 2) * 64;

    float acc[2][8][4] = {};

    auto stageA = [&](int c, int buf) {  // fp32 -> 2 bf16 planes
        const int row = tid >> 1;
        const int kh  = (tid & 1) * 16;
        const float* xr = x + (size_t)(tok0 + row) * DDIM + c * KC + kh;
        #pragma unroll
        for (int j = 0; j < 4; ++j) {
            float4 v = *(const float4*)(xr + j * 4);
            unsigned short h1[4], h2[4];
            split2(v.x, h1[0], h2[0]);
            split2(v.y, h1[1], h2[1]);
            split2(v.z, h1[2], h2[2]);
            split2(v.w, h1[3], h2[3]);
            unsigned boff = sw(row, (unsigned)((kh + j * 4) * 2));
            *(uint2*)(smbuf + a_plane(buf, 0) + row * 64 + boff) =
                make_uint2(h1[0] | ((unsigned)h1[1] << 16), h1[2] | ((unsigned)h1[3] << 16));
            *(uint2*)(smbuf + a_plane(buf, 1) + row * 64 + boff) =
                make_uint2(h2[0] | ((unsigned)h2[1] << 16), h2[2] | ((unsigned)h2[3] << 16));
        }
    };
    auto stageB = [&](int c, int buf) {  // bf16 planes gmem -> smem
        #pragma unroll
        for (int i = 0; i < 4; ++i) {
            int cdx = tid + 256 * i;          // 0..1023
            int p = cdx >> 9, rem = cdx & 511;
            int n = rem >> 2, kq = rem & 3;
            const unsigned short* src = g_wb + (size_t)p * 131072 + (size_t)n * DDIM + c * KC + kq * 8;
            unsigned dst = sb + b_plane(buf, p) + n * 64 + sw(n, (unsigned)(kq * 16));
            cp16(dst, src);
        }
    };

    stageB(0, 0);
    asm volatile("cp.async.commit_group;" ::: "memory");
    stageA(0, 0);

    for (int c = 0; c < NC; ++c) {
        const int buf = c & 1;
        if (c + 1 < NC) {
            stageB(c + 1, buf ^ 1);
            asm volatile("cp.async.commit_group;" ::: "memory");
            stageA(c + 1, buf ^ 1);
            asm volatile("cp.async.wait_group 1;" ::: "memory");
        } else {
            asm volatile("cp.async.wait_group 0;" ::: "memory");
        }
        __syncthreads();

        #pragma unroll
        for (int ks = 0; ks < 2; ++ks) {
            unsigned af[2][2][4];
            #pragma unroll
            for (int p = 0; p < 2; ++p)
                #pragma unroll
                for (int mt = 0; mt < 2; ++mt) {
                    int r = mrow + mt * 16 + (lane & 15);
                    unsigned addr = sb + a_plane(buf, p) + r * 64 +
                                    sw(r, (unsigned)(ks * 32 + (lane >> 4) * 16));
                    ldm4(af[p][mt], addr);
                }
            #pragma unroll
            for (int ntp = 0; ntp < 4; ++ntp) {
                unsigned bm[2][4];
                #pragma unroll
                for (int p = 0; p < 2; ++p) {
                    int n = ncol + ntp * 16 + (lane & 7) + ((lane >> 4) & 1) * 8;
                    unsigned addr = sb + b_plane(buf, p) + n * 64 +
                                    sw(n, (unsigned)(ks * 32 + ((lane >> 3) & 1) * 16));
                    ldm4(bm[p], addr);
                }
                #pragma unroll
                for (int mt = 0; mt < 2; ++mt)
                    #pragma unroll
                    for (int h = 0; h < 2; ++h) {
                        float* C = acc[mt][ntp * 2 + h];
                        mma_bf16(C, af[0][mt], bm[0][h * 2], bm[0][h * 2 + 1]);  // a1*b1
                        mma_bf16(C, af[0][mt], bm[1][h * 2], bm[1][h * 2 + 1]);  // a1*b2
                        mma_bf16(C, af[1][mt], bm[0][h * 2], bm[0][h * 2 + 1]);  // a2*b1
                    }
            }
        }
        __syncthreads();
    }

    // ---------------- epilogue ----------------
    float* canvas = (float*)smbuf;                         // [128][133]
    float* us     = (float*)(smbuf + US_BASE);             // [128][65]
    unsigned* badlist = (unsigned*)(smbuf + BAD_BASE);
    int* cnt = (int*)(smbuf + CNT_BASE);

    #pragma unroll
    for (int mt = 0; mt < 2; ++mt)
        #pragma unroll
        for (int nt = 0; nt < 8; ++nt) {
            int r = mrow + mt * 16 + (lane >> 2);
            int cc = ncol + nt * 8 + (lane & 3) * 2;
            canvas[r * CV_STRIDE + cc]           = acc[mt][nt][0];
            canvas[r * CV_STRIDE + cc + 1]       = acc[mt][nt][1];
            canvas[(r + 8) * CV_STRIDE + cc]     = acc[mt][nt][2];
            canvas[(r + 8) * CV_STRIDE + cc + 1] = acc[mt][nt][3];
        }
    #pragma unroll
    for (int i = 0; i < 8; ++i) {
        int lin4 = tid + 256 * i;             // 0..2047 float4s
        int tr = lin4 >> 4, kk = (lin4 & 15) * 4;
        float4 v = *(const float4*)(u + (size_t)(tok0 + tr) * NEXP + kk);
        us[tr * US_STRIDE + kk]     = v.x;
        us[tr * US_STRIDE + kk + 1] = v.y;
        us[tr * US_STRIDE + kk + 2] = v.z;
        us[tr * US_STRIDE + kk + 3] = v.w;
    }
    if (tid == 0) *cnt = 0;
    __syncthreads();

    // pass 1: per-token top-4 scan on TC logits, finalize, flag marginal tokens
    if (tid < TILE_M) {
        const int t = tid;
        const size_t tg = (size_t)(tok0 + t);
        float m0 = -INFINITY, m1 = -INFINITY, m2 = -INFINITY, m3 = -INFINITY;
        int x0 = 0, x1 = 0, x2 = 0, x3 = 0;
        #pragma unroll 8
        for (int e = 0; e < NEXP; ++e) {
            float nz = canvas[t * CV_STRIDE + 64 + e] + bn[e];
            float v  = canvas[t * CV_STRIDE + e] + br[e] +
                       us[t * US_STRIDE + e] * softplus_f(nz);
            if (v > m0)      { m3=m2; x3=x2; m2=m1; x2=x1; m1=m0; x1=x0; m0=v; x0=e; }
            else if (v > m1) { m3=m2; x3=x2; m2=m1; x2=x1; m1=v; x1=e; }
            else if (v > m2) { m3=m2; x3=x2; m2=v; x2=e; }
            else if (v > m3) { m3=v; x3=e; }
        }
        float ex  = expf(m1 - m0);
        float inv = 1.0f / (1.0f + ex);
        float p1 = inv, p2 = ex * inv;

        float* rowp = out + tg * NEXP;
        #pragma unroll
        for (int q = 0; q < NEXP / 4; ++q) {
            int eb = q * 4;
            float4 v;
            v.x = (eb + 0 == x0) ? p1 : ((eb + 0 == x1) ? p2 : 0.0f);
            v.y = (eb + 1 == x0) ? p1 : ((eb + 1 == x1) ? p2 : 0.0f);
            v.z = (eb + 2 == x0) ? p1 : ((eb + 2 == x1) ? p2 : 0.0f);
            v.w = (eb + 3 == x0) ? p1 : ((eb + 3 == x1) ? p2 : 0.0f);
            ((float4*)rowp)[q] = v;
        }
        *(float2*)(out + (size_t)NTOK * NEXP + tg * 2) = make_float2((float)x0, (float)x1);

        if ((m0 - m1 < EPS_MARGIN) || (m1 - m2 < EPS_MARGIN)) {
            int pos = atomicAdd(cnt, 1);
            badlist[pos] = (unsigned)t | ((unsigned)x0 << 7) | ((unsigned)x1 << 13) |
                           ((unsigned)x2 << 19) | ((unsigned)x3 << 25);
        }
    }
    __syncthreads();

    // pass 2: re-check marginal tokens with REFERENCE-ORDER fp32 chains.
    // Each candidate logit is recomputed as a single-accumulator, ascending-k
    // sequential fmaf chain — the exact summation order of the round-5 kernel
    // that matched the reference on every token of this dataset.
    const int nbad = *cnt;
    for (int b = wid; b < nbad; b += 8) {
        unsigned pk = badlist[b];
        int t = pk & 127;
        int cd[4] = { (int)((pk >> 7) & 63), (int)((pk >> 13) & 63),
                      (int)((pk >> 19) & 63), (int)((pk >> 25) & 63) };
        float l = 0.0f;
        if (lane < 8) {
            int q = lane & 3;
            int n = cd[q] + ((lane >= 4) ? 64 : 0);   // lanes 0-3 route, 4-7 noise
            const float* xp = x + (size_t)(tok0 + t) * DDIM;
            const float* wp = g_wt + (size_t)n * DDIM;
            #pragma unroll 8
            for (int k = 0; k < DDIM; ++k)
                l = fmaf(xp[k], wp[k], l);
        }
        float ar[4], an[4];
        #pragma unroll
        for (int q = 0; q < 4; ++q) {
            ar[q] = __shfl_sync(0xFFFFFFFFu, l, q);
            an[q] = __shfl_sync(0xFFFFFFFFu, l, 4 + q);
        }
        // all lanes rank redundantly (cheap, avoids broadcasts)
        float nv[4];
        #pragma unroll
        for (int q = 0; q < 4; ++q)
            nv[q] = ar[q] + br[cd[q]] +
                    us[t * US_STRIDE + cd[q]] * softplus_f(an[q] + bn[cd[q]]);
        int b1 = 0;
        #pragma unroll
        for (int q = 1; q < 4; ++q)
            if (nv[q] > nv[b1] || (nv[q] == nv[b1] && cd[q] < cd[b1])) b1 = q;
        int b2 = (b1 == 0) ? 1 : 0;
        #pragma unroll
        for (int q = 0; q < 4; ++q)
            if (q != b1 && (nv[q] > nv[b2] || (nv[q] == nv[b2] && cd[q] < cd[b2]))) b2 = q;
        float ex  = expf(nv[b2] - nv[b1]);
        float inv = 1.0f / (1.0f + ex);
        float p1 = inv, p2 = ex * inv;
        int i1 = cd[b1], i2 = cd[b2];

        float* rowp = out + (size_t)(tok0 + t) * NEXP;
        #pragma unroll
        for (int e = lane; e < NEXP; e += 32)
            rowp[e] = (e == i1) ? p1 : ((e == i2) ? p2 : 0.0f);
        if (lane == 0)
            *(float2*)(out + (size_t)NTOK * NEXP + (size_t)(tok0 + t) * 2) =
                make_float2((float)i1, (float)i2);
    }
}

extern "C" void kernel_launch(void* const* d_in, const int* in_sizes, int n_in,
                              void* d_out, int out_size) {
    const float* x  = (const float*)d_in[0];  // mh_output [B,T,D]
    const float* Wr = (const float*)d_in[1];  // W_route   [D,E]
    const float* br = (const float*)d_in[2];  // b_route   [E]
    const float* Wn = (const float*)d_in[3];  // W_noise   [D,E]
    const float* bn = (const float*)d_in[4];  // b_noise   [E]
    const float* u  = (const float*)d_in[5];  // noise_u   [B,T,E]

    cudaFuncSetAttribute(router_mma_kernel,
                         cudaFuncAttributeMaxDynamicSharedMemorySize, SMEM_TOTAL);

    prep_w<<<512, 256>>>(Wr, Wn);
    router_mma_kernel<<<NCTA, THREADS, SMEM_TOTAL>>>(x, br, bn, u, (float*)d_out);
}